// round 13
// baseline (speedup 1.0000x reference)
#include <cuda_runtime.h>
#include <math.h>

// ---------------- problem constants ----------------
namespace {
constexpr int B_   = 32768;
constexpr int IN_  = 512;
constexpr int E_   = 8;
constexpr int H_   = 128;
constexpr int MO_  = 256;
constexpr int OUT_ = 2;

constexpr int TM = 64;    // tokens per expert tile
constexpr int XS = 65;    // s_xc row stride (pad: cross-half-warp bank decorrelation)
constexpr int HS = 132;   // s_h row stride (pad, multiple of 4 for float4)

constexpr int SMEM_EXPERT_FLOATS = TM * XS    // x chunk   (4160)
                                 + 64 * H_    // w chunk   (8192)  (reused for W2 32x256)
                                 + TM * HS    // h         (8448)
                                 + MO_ * OUT_ // wout      (512)
                                 + TM         // gates     (64)
                                 + TM;        // tokens    (64)
constexpr int SMEM_EXPERT_BYTES = SMEM_EXPERT_FLOATS * 4;
}

// ---------------- device scratch (no allocations allowed) ----------------
__device__ int   g_cnt[E_];
__device__ float g_imp[E_];
__device__ float g_load[E_];
__device__ int   g_btok[E_ * B_];
__device__ float g_bgate[E_ * B_];

// ---------------- packed fp32x2 helpers (Blackwell 2x fp32 rate) ----------------
__device__ __forceinline__ unsigned long long pack2f(float v) {
    unsigned long long r;
    asm("mov.b64 %0, {%1, %1};" : "=l"(r) : "f"(v));
    return r;
}
__device__ __forceinline__ void ffma2(unsigned long long &d, unsigned long long a, unsigned long long b) {
    asm("fma.rn.f32x2 %0, %1, %2, %0;" : "+l"(d) : "l"(a), "l"(b));
}
__device__ __forceinline__ float2 unpack2f(unsigned long long v) {
    float lo, hi;
    asm("mov.b64 {%0, %1}, %2;" : "=f"(lo), "=f"(hi) : "l"(v));
    return make_float2(lo, hi);
}

// ---------------- init: out = bout, reset counters ----------------
__global__ void init_kernel(float* __restrict__ out, const float* __restrict__ bout) {
    int idx = blockIdx.x * blockDim.x + threadIdx.x;
    if (idx < B_ * OUT_) out[idx] = bout[idx & (OUT_ - 1)];
    if (idx < E_) { g_cnt[idx] = 0; g_imp[idx] = 0.f; g_load[idx] = 0.f; }
}

// ---------------- gating: logits, top-2, softmax, scatter to buckets ----------------
__global__ __launch_bounds__(1024) void gate_kernel(
    const float* __restrict__ x, const float* __restrict__ wg)
{
    __shared__ float s_w[E_ * IN_];   // transposed w_gate: [e][i]
    __shared__ float s_imp[E_];
    __shared__ int   s_loc[E_];
    __shared__ int   s_base[E_];
    __shared__ int   s_e[32][2];
    __shared__ float s_g[32][2];
    __shared__ int   s_pos[32][2];

    const int tid  = threadIdx.x;
    const int warp = tid >> 5;
    const int lane = tid & 31;

    for (int idx = tid; idx < IN_ * E_; idx += 1024) {
        int i = idx >> 3, e = idx & 7;
        s_w[e * IN_ + i] = wg[idx];
    }
    if (tid < E_) { s_imp[tid] = 0.f; s_loc[tid] = 0; }
    __syncthreads();

    const int tok = blockIdx.x * 32 + warp;
    const float* xr = x + (size_t)tok * IN_;

    float acc[E_];
    #pragma unroll
    for (int e = 0; e < E_; ++e) acc[e] = 0.f;

    #pragma unroll 4
    for (int j = 0; j < IN_ / 32; ++j) {
        float xv = xr[lane + 32 * j];
        #pragma unroll
        for (int e = 0; e < E_; ++e)
            acc[e] = fmaf(xv, s_w[e * IN_ + lane + 32 * j], acc[e]);
    }
    #pragma unroll
    for (int e = 0; e < E_; ++e) {
        #pragma unroll
        for (int off = 16; off >= 1; off >>= 1)
            acc[e] += __shfl_xor_sync(0xffffffffu, acc[e], off);
    }

    if (lane == 0) {
        int e0 = 0, e1 = -1;
        float v0 = acc[0], v1 = -1e30f;
        #pragma unroll
        for (int e = 1; e < E_; ++e) {
            float v = acc[e];
            if (v > v0) { v1 = v0; e1 = e0; v0 = v; e0 = e; }
            else if (v > v1) { v1 = v; e1 = e; }
        }
        float g0 = 1.f / (1.f + __expf(v1 - v0));
        float g1 = 1.f - g0;
        atomicAdd(&s_imp[e0], g0);
        atomicAdd(&s_imp[e1], g1);
        s_pos[warp][0] = atomicAdd(&s_loc[e0], 1);
        s_pos[warp][1] = atomicAdd(&s_loc[e1], 1);
        s_e[warp][0] = e0; s_e[warp][1] = e1;
        s_g[warp][0] = g0; s_g[warp][1] = g1;
    }
    __syncthreads();

    if (tid < E_) {
        int c = s_loc[tid];
        s_base[tid] = atomicAdd(&g_cnt[tid], c);
        atomicAdd(&g_imp[tid], s_imp[tid]);
        atomicAdd(&g_load[tid], (float)c);
    }
    __syncthreads();

    if (lane == 0) {
        #pragma unroll
        for (int k = 0; k < 2; ++k) {
            int e = s_e[warp][k];
            int p = s_base[e] + s_pos[warp][k];
            g_btok[e * B_ + p]  = tok;
            g_bgate[e * B_ + p] = s_g[warp][k];
        }
    }
}

// ---------------- expert MLP: gather -> GEMM1(relu) -> GEMM2 -> softmax -> out atomics ----------------
__global__ __launch_bounds__(256) void expert_kernel(
    const float* __restrict__ x,
    const float* __restrict__ W1, const float* __restrict__ b1,
    const float* __restrict__ W2, const float* __restrict__ b2,
    const float* __restrict__ Wout,
    float* __restrict__ out)
{
    const int e    = blockIdx.y;
    const int cnt  = g_cnt[e];
    const int base = blockIdx.x * TM;
    if (base >= cnt) return;

    extern __shared__ float smem[];
    float* s_xc   = smem;                    // TM*XS
    float* s_w    = s_xc + TM * XS;          // 64*H_  (also 32*MO_)
    float* s_h    = s_w + 64 * H_;           // TM*HS
    float* s_wout = s_h + TM * HS;           // MO_*OUT_
    float* s_gate = s_wout + MO_ * OUT_;     // TM
    int*   s_tok  = (int*)(s_gate + TM);     // TM

    const int tid  = threadIdx.x;
    const int warp = tid >> 5;
    const int lane = tid & 31;
    const int hf   = lane >> 4;
    const int cl   = lane & 15;
    const int r0   = warp * 8 + hf * 4;   // 4 rows per thread
    const int cA   = cl * 4;              // base col within a 64-col group

    if (tid < TM) {
        int idx = base + tid;
        if (idx < cnt) { s_tok[tid] = g_btok[e * B_ + idx]; s_gate[tid] = g_bgate[e * B_ + idx]; }
        else           { s_tok[tid] = 0;                    s_gate[tid] = 0.f; }
    }
    for (int i = tid; i < MO_ * OUT_; i += 256) s_wout[i] = Wout[i];
    __syncthreads();

    // ===== GEMM1: h[TM,128] = relu(X[TM,512] @ W1[e] + b1[e]) =====
    unsigned long long acc1[16];
    #pragma unroll
    for (int i = 0; i < 16; ++i) acc1[i] = 0ull;

    for (int kc = 0; kc < IN_ / 64; ++kc) {
        for (int idx = tid; idx < TM * 64; idx += 256) {
            int r = idx >> 6, i = idx & 63;
            s_xc[r * XS + i] = x[(size_t)s_tok[r] * IN_ + kc * 64 + i];
        }
        const float* w1p = W1 + ((size_t)e * IN_ + (size_t)kc * 64) * H_;
        for (int idx = tid; idx < 64 * H_; idx += 256) s_w[idx] = w1p[idx];
        __syncthreads();

        #pragma unroll 4
        for (int kk = 0; kk < 64; ++kk) {
            const float* wr = s_w + kk * H_;
            ulonglong2 wa = *(const ulonglong2*)(wr + cA);
            ulonglong2 wb = *(const ulonglong2*)(wr + 64 + cA);
            #pragma unroll
            for (int r = 0; r < 4; ++r) {
                unsigned long long xv = pack2f(s_xc[(r0 + r) * XS + kk]);
                ffma2(acc1[r * 4 + 0], xv, wa.x);
                ffma2(acc1[r * 4 + 1], xv, wa.y);
                ffma2(acc1[r * 4 + 2], xv, wb.x);
                ffma2(acc1[r * 4 + 3], xv, wb.y);
            }
        }
        __syncthreads();
    }

    { // bias + relu -> s_h
        const float* b1p = b1 + e * H_;
        float bA0 = b1p[cA], bA1 = b1p[cA + 1], bA2 = b1p[cA + 2], bA3 = b1p[cA + 3];
        float bB0 = b1p[64 + cA], bB1 = b1p[64 + cA + 1], bB2 = b1p[64 + cA + 2], bB3 = b1p[64 + cA + 3];
        #pragma unroll
        for (int r = 0; r < 4; ++r) {
            float2 a0 = unpack2f(acc1[r * 4 + 0]);
            float2 a1 = unpack2f(acc1[r * 4 + 1]);
            float2 a2 = unpack2f(acc1[r * 4 + 2]);
            float2 a3 = unpack2f(acc1[r * 4 + 3]);
            float4 hA = make_float4(fmaxf(a0.x + bA0, 0.f), fmaxf(a0.y + bA1, 0.f),
                                    fmaxf(a1.x + bA2, 0.f), fmaxf(a1.y + bA3, 0.f));
            float4 hB = make_float4(fmaxf(a2.x + bB0, 0.f), fmaxf(a2.y + bB1, 0.f),
                                    fmaxf(a3.x + bB2, 0.f), fmaxf(a3.y + bB3, 0.f));
            *(float4*)(s_h + (r0 + r) * HS + cA)      = hA;
            *(float4*)(s_h + (r0 + r) * HS + 64 + cA) = hB;
        }
    }
    // (visibility of s_h covered by the first __syncthreads in the GEMM2 chunk loop)

    // ===== GEMM2: P[TM,256] = h @ W2[e] + b2[e] =====
    unsigned long long acc2[32];
    #pragma unroll
    for (int i = 0; i < 32; ++i) acc2[i] = 0ull;

    for (int kc = 0; kc < H_ / 32; ++kc) {
        const float* w2p = W2 + ((size_t)e * H_ + (size_t)kc * 32) * MO_;
        for (int idx = tid; idx < 32 * MO_; idx += 256) s_w[idx] = w2p[idx];
        __syncthreads();

        #pragma unroll 2
        for (int kk = 0; kk < 32; ++kk) {
            const float* wr = s_w + kk * MO_;
            ulonglong2 w0 = *(const ulonglong2*)(wr + cA);
            ulonglong2 w1 = *(const ulonglong2*)(wr + 64 + cA);
            ulonglong2 w2 = *(const ulonglong2*)(wr + 128 + cA);
            ulonglong2 w3 = *(const ulonglong2*)(wr + 192 + cA);
            #pragma unroll
            for (int r = 0; r < 4; ++r) {
                unsigned long long xv = pack2f(s_h[(r0 + r) * HS + kc * 32 + kk]);
                ffma2(acc2[r * 8 + 0], xv, w0.x);
                ffma2(acc2[r * 8 + 1], xv, w0.y);
                ffma2(acc2[r * 8 + 2], xv, w1.x);
                ffma2(acc2[r * 8 + 3], xv, w1.y);
                ffma2(acc2[r * 8 + 4], xv, w2.x);
                ffma2(acc2[r * 8 + 5], xv, w2.y);
                ffma2(acc2[r * 8 + 6], xv, w3.x);
                ffma2(acc2[r * 8 + 7], xv, w3.y);
            }
        }
        __syncthreads();
    }

    // ===== softmax over MO=256 per row (half-warp owns a row) + fused Wout + atomics =====
    const float* b2p = b2 + e * MO_;
    float b2r[16];
    #pragma unroll
    for (int g = 0; g < 4; ++g) {
        b2r[g * 4 + 0] = b2p[g * 64 + cA];
        b2r[g * 4 + 1] = b2p[g * 64 + cA + 1];
        b2r[g * 4 + 2] = b2p[g * 64 + cA + 2];
        b2r[g * 4 + 3] = b2p[g * 64 + cA + 3];
    }

    #pragma unroll
    for (int r = 0; r < 4; ++r) {
        float p[16];
        #pragma unroll
        for (int g = 0; g < 4; ++g) {
            float2 lo = unpack2f(acc2[r * 8 + g * 2 + 0]);
            float2 hi = unpack2f(acc2[r * 8 + g * 2 + 1]);
            p[g * 4 + 0] = lo.x + b2r[g * 4 + 0];
            p[g * 4 + 1] = lo.y + b2r[g * 4 + 1];
            p[g * 4 + 2] = hi.x + b2r[g * 4 + 2];
            p[g * 4 + 3] = hi.y + b2r[g * 4 + 3];
        }
        float mx = p[0];
        #pragma unroll
        for (int j = 1; j < 16; ++j) mx = fmaxf(mx, p[j]);
        #pragma unroll
        for (int off = 8; off >= 1; off >>= 1)
            mx = fmaxf(mx, __shfl_xor_sync(0xffffffffu, mx, off));

        float s = 0.f, o0 = 0.f, o1 = 0.f;
        #pragma unroll
        for (int j = 0; j < 16; ++j) {
            int col = (j >> 2) * 64 + cA + (j & 3);
            float ev = __expf(p[j] - mx);
            s += ev;
            o0 = fmaf(ev, s_wout[col * 2 + 0], o0);
            o1 = fmaf(ev, s_wout[col * 2 + 1], o1);
        }
        #pragma unroll
        for (int off = 8; off >= 1; off >>= 1) {
            s  += __shfl_xor_sync(0xffffffffu, s, off);
            o0 += __shfl_xor_sync(0xffffffffu, o0, off);
            o1 += __shfl_xor_sync(0xffffffffu, o1, off);
        }
        if (cl == 0) {
            int rg = r0 + r;
            if (base + rg < cnt) {
                float gsc = s_gate[rg] / s;
                size_t ob = (size_t)s_tok[rg] * OUT_;
                atomicAdd(out + ob + 0, o0 * gsc);
                atomicAdd(out + ob + 1, o1 * gsc);
            }
        }
    }
}

// ---------------- loss: cv^2(importance) + cv^2(load), ddof=1 ----------------
__global__ void loss_kernel(float* __restrict__ out, int out_size) {
    if (threadIdx.x != 0 || blockIdx.x != 0) return;
    double vi[E_], vl[E_], si = 0.0, sl = 0.0;
    for (int e = 0; e < E_; ++e) { vi[e] = (double)g_imp[e]; vl[e] = (double)g_load[e]; si += vi[e]; sl += vl[e]; }
    double mi = si / E_, ml = sl / E_;
    double qi = 0.0, ql = 0.0;
    for (int e = 0; e < E_; ++e) { double di = vi[e] - mi, dl = vl[e] - ml; qi += di * di; ql += dl * dl; }
    qi /= (E_ - 1); ql /= (E_ - 1);
    double loss = (qi / (mi * mi + 1e-10) + ql / (ml * ml + 1e-10)) * 1e-2;
    if (out_size > B_ * OUT_) out[B_ * OUT_] = (float)loss;
}

// ---------------- launch ----------------
extern "C" void kernel_launch(void* const* d_in, const int* in_sizes, int n_in,
                              void* d_out, int out_size) {
    (void)in_sizes; (void)n_in;
    const float* x    = (const float*)d_in[0];
    // d_in[1] = cat_prop (unused by the reference's output path)
    const float* wg   = (const float*)d_in[2];
    const float* W1   = (const float*)d_in[3];
    const float* b1   = (const float*)d_in[4];
    const float* W2   = (const float*)d_in[5];
    const float* b2   = (const float*)d_in[6];
    const float* Wout = (const float*)d_in[7];
    const float* bout = (const float*)d_in[8];
    float* out = (float*)d_out;

    cudaFuncSetAttribute(expert_kernel, cudaFuncAttributeMaxDynamicSharedMemorySize,
                         SMEM_EXPERT_BYTES);

    init_kernel<<<(B_ * OUT_ + 255) / 256, 256>>>(out, bout);
    gate_kernel<<<B_ / 32, 1024>>>(x, wg);
    expert_kernel<<<dim3(B_ / TM, E_), 256, SMEM_EXPERT_BYTES>>>(x, W1, b1, W2, b2, Wout, out);
    loss_kernel<<<1, 32>>>(out, out_size);
}

// round 14
// speedup vs baseline: 1.0040x; 1.0040x over previous
#include <cuda_runtime.h>
#include <math.h>

// ---------------- problem constants ----------------
namespace {
constexpr int B_   = 32768;
constexpr int IN_  = 512;
constexpr int E_   = 8;
constexpr int H_   = 128;
constexpr int MO_  = 256;
constexpr int OUT_ = 2;

constexpr int TM = 64;    // tokens per expert tile
constexpr int XS = 65;    // s_xc row stride (pad: cross-half-warp bank decorrelation)
constexpr int HS = 132;   // s_h row stride (pad, multiple of 4 for float4)

constexpr int SMEM_EXPERT_FLOATS = TM * XS    // x chunk   (4160)
                                 + 64 * H_    // w chunk   (8192)  (reused for W2 32x256)
                                 + TM * HS    // h         (8448)
                                 + MO_ * OUT_ // wout      (512)
                                 + TM         // gates     (64)
                                 + TM;        // tokens    (64)
constexpr int SMEM_EXPERT_BYTES = SMEM_EXPERT_FLOATS * 4;
}

// ---------------- device scratch (no allocations allowed) ----------------
__device__ int   g_cnt[E_];
__device__ float g_imp[E_];
__device__ float g_load[E_];
__device__ int   g_btok[E_ * B_];
__device__ float g_bgate[E_ * B_];

// ---------------- packed fp32x2 helpers (Blackwell 2x fp32 rate) ----------------
__device__ __forceinline__ unsigned long long pack2f(float v) {
    unsigned long long r;
    asm("mov.b64 %0, {%1, %1};" : "=l"(r) : "f"(v));
    return r;
}
__device__ __forceinline__ void ffma2(unsigned long long &d, unsigned long long a, unsigned long long b) {
    asm("fma.rn.f32x2 %0, %1, %2, %0;" : "+l"(d) : "l"(a), "l"(b));
}
__device__ __forceinline__ float2 unpack2f(unsigned long long v) {
    float lo, hi;
    asm("mov.b64 {%0, %1}, %2;" : "=f"(lo), "=f"(hi) : "l"(v));
    return make_float2(lo, hi);
}

// ---------------- init: out = bout, reset counters ----------------
__global__ void init_kernel(float* __restrict__ out, const float* __restrict__ bout) {
    int idx = blockIdx.x * blockDim.x + threadIdx.x;
    if (idx < B_ * OUT_) out[idx] = bout[idx & (OUT_ - 1)];
    if (idx < E_) { g_cnt[idx] = 0; g_imp[idx] = 0.f; g_load[idx] = 0.f; }
}

// ---------------- gating: logits, top-2, softmax, scatter to buckets ----------------
__global__ __launch_bounds__(1024) void gate_kernel(
    const float* __restrict__ x, const float* __restrict__ wg)
{
    __shared__ float s_w[E_ * IN_];   // transposed w_gate: [e][i]
    __shared__ float s_imp[E_];
    __shared__ int   s_loc[E_];
    __shared__ int   s_base[E_];
    __shared__ int   s_e[32][2];
    __shared__ float s_g[32][2];
    __shared__ int   s_pos[32][2];

    const int tid  = threadIdx.x;
    const int warp = tid >> 5;
    const int lane = tid & 31;

    for (int idx = tid; idx < IN_ * E_; idx += 1024) {
        int i = idx >> 3, e = idx & 7;
        s_w[e * IN_ + i] = wg[idx];
    }
    if (tid < E_) { s_imp[tid] = 0.f; s_loc[tid] = 0; }
    __syncthreads();

    const int tok = blockIdx.x * 32 + warp;
    const float* xr = x + (size_t)tok * IN_;

    float acc[E_];
    #pragma unroll
    for (int e = 0; e < E_; ++e) acc[e] = 0.f;

    #pragma unroll 4
    for (int j = 0; j < IN_ / 32; ++j) {
        float xv = xr[lane + 32 * j];
        #pragma unroll
        for (int e = 0; e < E_; ++e)
            acc[e] = fmaf(xv, s_w[e * IN_ + lane + 32 * j], acc[e]);
    }
    #pragma unroll
    for (int e = 0; e < E_; ++e) {
        #pragma unroll
        for (int off = 16; off >= 1; off >>= 1)
            acc[e] += __shfl_xor_sync(0xffffffffu, acc[e], off);
    }

    if (lane == 0) {
        int e0 = 0, e1 = -1;
        float v0 = acc[0], v1 = -1e30f;
        #pragma unroll
        for (int e = 1; e < E_; ++e) {
            float v = acc[e];
            if (v > v0) { v1 = v0; e1 = e0; v0 = v; e0 = e; }
            else if (v > v1) { v1 = v; e1 = e; }
        }
        float g0 = 1.f / (1.f + __expf(v1 - v0));
        float g1 = 1.f - g0;
        atomicAdd(&s_imp[e0], g0);
        atomicAdd(&s_imp[e1], g1);
        s_pos[warp][0] = atomicAdd(&s_loc[e0], 1);
        s_pos[warp][1] = atomicAdd(&s_loc[e1], 1);
        s_e[warp][0] = e0; s_e[warp][1] = e1;
        s_g[warp][0] = g0; s_g[warp][1] = g1;
    }
    __syncthreads();

    if (tid < E_) {
        int c = s_loc[tid];
        s_base[tid] = atomicAdd(&g_cnt[tid], c);
        atomicAdd(&g_imp[tid], s_imp[tid]);
        atomicAdd(&g_load[tid], (float)c);
    }
    __syncthreads();

    if (lane == 0) {
        #pragma unroll
        for (int k = 0; k < 2; ++k) {
            int e = s_e[warp][k];
            int p = s_base[e] + s_pos[warp][k];
            g_btok[e * B_ + p]  = tok;
            g_bgate[e * B_ + p] = s_g[warp][k];
        }
    }
}

// ---------------- expert MLP: gather -> GEMM1(relu) -> GEMM2 -> softmax -> out atomics ----------------
__global__ __launch_bounds__(256) void expert_kernel(
    const float* __restrict__ x,
    const float* __restrict__ W1, const float* __restrict__ b1,
    const float* __restrict__ W2, const float* __restrict__ b2,
    const float* __restrict__ Wout,
    float* __restrict__ out)
{
    const int e    = blockIdx.y;
    const int cnt  = g_cnt[e];
    const int base = blockIdx.x * TM;
    if (base >= cnt) return;

    extern __shared__ float smem[];
    float* s_xc   = smem;                    // TM*XS
    float* s_w    = s_xc + TM * XS;          // 64*H_  (also 32*MO_)
    float* s_h    = s_w + 64 * H_;           // TM*HS
    float* s_wout = s_h + TM * HS;           // MO_*OUT_
    float* s_gate = s_wout + MO_ * OUT_;     // TM
    int*   s_tok  = (int*)(s_gate + TM);     // TM

    const int tid  = threadIdx.x;
    const int warp = tid >> 5;
    const int lane = tid & 31;
    const int hf   = lane >> 4;
    const int cl   = lane & 15;
    const int r0   = warp * 8 + hf * 4;   // 4 rows per thread
    const int cA   = cl * 4;              // base col within a 64-col group

    if (tid < TM) {
        int idx = base + tid;
        if (idx < cnt) { s_tok[tid] = g_btok[e * B_ + idx]; s_gate[tid] = g_bgate[e * B_ + idx]; }
        else           { s_tok[tid] = 0;                    s_gate[tid] = 0.f; }
    }
    for (int i = tid; i < MO_ * OUT_; i += 256) s_wout[i] = Wout[i];
    __syncthreads();

    // ===== GEMM1: h[TM,128] = relu(X[TM,512] @ W1[e] + b1[e]) =====
    unsigned long long acc1[16];
    #pragma unroll
    for (int i = 0; i < 16; ++i) acc1[i] = 0ull;

    for (int kc = 0; kc < IN_ / 64; ++kc) {
        for (int idx = tid; idx < TM * 64; idx += 256) {
            int r = idx >> 6, i = idx & 63;
            s_xc[r * XS + i] = x[(size_t)s_tok[r] * IN_ + kc * 64 + i];
        }
        const float* w1p = W1 + ((size_t)e * IN_ + (size_t)kc * 64) * H_;
        for (int idx = tid; idx < 64 * H_; idx += 256) s_w[idx] = w1p[idx];
        __syncthreads();

        #pragma unroll 4
        for (int kk = 0; kk < 64; ++kk) {
            const float* wr = s_w + kk * H_;
            ulonglong2 wa = *(const ulonglong2*)(wr + cA);
            ulonglong2 wb = *(const ulonglong2*)(wr + 64 + cA);
            #pragma unroll
            for (int r = 0; r < 4; ++r) {
                unsigned long long xv = pack2f(s_xc[(r0 + r) * XS + kk]);
                ffma2(acc1[r * 4 + 0], xv, wa.x);
                ffma2(acc1[r * 4 + 1], xv, wa.y);
                ffma2(acc1[r * 4 + 2], xv, wb.x);
                ffma2(acc1[r * 4 + 3], xv, wb.y);
            }
        }
        __syncthreads();
    }

    { // bias + relu -> s_h
        const float* b1p = b1 + e * H_;
        float bA0 = b1p[cA], bA1 = b1p[cA + 1], bA2 = b1p[cA + 2], bA3 = b1p[cA + 3];
        float bB0 = b1p[64 + cA], bB1 = b1p[64 + cA + 1], bB2 = b1p[64 + cA + 2], bB3 = b1p[64 + cA + 3];
        #pragma unroll
        for (int r = 0; r < 4; ++r) {
            float2 a0 = unpack2f(acc1[r * 4 + 0]);
            float2 a1 = unpack2f(acc1[r * 4 + 1]);
            float2 a2 = unpack2f(acc1[r * 4 + 2]);
            float2 a3 = unpack2f(acc1[r * 4 + 3]);
            float4 hA = make_float4(fmaxf(a0.x + bA0, 0.f), fmaxf(a0.y + bA1, 0.f),
                                    fmaxf(a1.x + bA2, 0.f), fmaxf(a1.y + bA3, 0.f));
            float4 hB = make_float4(fmaxf(a2.x + bB0, 0.f), fmaxf(a2.y + bB1, 0.f),
                                    fmaxf(a3.x + bB2, 0.f), fmaxf(a3.y + bB3, 0.f));
            *(float4*)(s_h + (r0 + r) * HS + cA)      = hA;
            *(float4*)(s_h + (r0 + r) * HS + 64 + cA) = hB;
        }
    }
    // (visibility of s_h covered by the first __syncthreads in the GEMM2 chunk loop)

    // ===== GEMM2: P[TM,256] = h @ W2[e] + b2[e] =====
    unsigned long long acc2[32];
    #pragma unroll
    for (int i = 0; i < 32; ++i) acc2[i] = 0ull;

    for (int kc = 0; kc < H_ / 32; ++kc) {
        const float* w2p = W2 + ((size_t)e * H_ + (size_t)kc * 32) * MO_;
        for (int idx = tid; idx < 32 * MO_; idx += 256) s_w[idx] = w2p[idx];
        __syncthreads();

        #pragma unroll 2
        for (int kk = 0; kk < 32; ++kk) {
            const float* wr = s_w + kk * MO_;
            ulonglong2 w0 = *(const ulonglong2*)(wr + cA);
            ulonglong2 w1 = *(const ulonglong2*)(wr + 64 + cA);
            ulonglong2 w2 = *(const ulonglong2*)(wr + 128 + cA);
            ulonglong2 w3 = *(const ulonglong2*)(wr + 192 + cA);
            #pragma unroll
            for (int r = 0; r < 4; ++r) {
                unsigned long long xv = pack2f(s_h[(r0 + r) * HS + kc * 32 + kk]);
                ffma2(acc2[r * 8 + 0], xv, w0.x);
                ffma2(acc2[r * 8 + 1], xv, w0.y);
                ffma2(acc2[r * 8 + 2], xv, w1.x);
                ffma2(acc2[r * 8 + 3], xv, w1.y);
                ffma2(acc2[r * 8 + 4], xv, w2.x);
                ffma2(acc2[r * 8 + 5], xv, w2.y);
                ffma2(acc2[r * 8 + 6], xv, w3.x);
                ffma2(acc2[r * 8 + 7], xv, w3.y);
            }
        }
        __syncthreads();
    }

    // ===== softmax over MO=256 per row (half-warp owns a row) + fused Wout + atomics =====
    const float* b2p = b2 + e * MO_;
    float b2r[16];
    #pragma unroll
    for (int g = 0; g < 4; ++g) {
        b2r[g * 4 + 0] = b2p[g * 64 + cA];
        b2r[g * 4 + 1] = b2p[g * 64 + cA + 1];
        b2r[g * 4 + 2] = b2p[g * 64 + cA + 2];
        b2r[g * 4 + 3] = b2p[g * 64 + cA + 3];
    }

    #pragma unroll
    for (int r = 0; r < 4; ++r) {
        float p[16];
        #pragma unroll
        for (int g = 0; g < 4; ++g) {
            float2 lo = unpack2f(acc2[r * 8 + g * 2 + 0]);
            float2 hi = unpack2f(acc2[r * 8 + g * 2 + 1]);
            p[g * 4 + 0] = lo.x + b2r[g * 4 + 0];
            p[g * 4 + 1] = lo.y + b2r[g * 4 + 1];
            p[g * 4 + 2] = hi.x + b2r[g * 4 + 2];
            p[g * 4 + 3] = hi.y + b2r[g * 4 + 3];
        }
        float mx = p[0];
        #pragma unroll
        for (int j = 1; j < 16; ++j) mx = fmaxf(mx, p[j]);
        #pragma unroll
        for (int off = 8; off >= 1; off >>= 1)
            mx = fmaxf(mx, __shfl_xor_sync(0xffffffffu, mx, off));

        float s = 0.f, o0 = 0.f, o1 = 0.f;
        #pragma unroll
        for (int j = 0; j < 16; ++j) {
            int col = (j >> 2) * 64 + cA + (j & 3);
            float ev = __expf(p[j] - mx);
            s += ev;
            o0 = fmaf(ev, s_wout[col * 2 + 0], o0);
            o1 = fmaf(ev, s_wout[col * 2 + 1], o1);
        }
        #pragma unroll
        for (int off = 8; off >= 1; off >>= 1) {
            s  += __shfl_xor_sync(0xffffffffu, s, off);
            o0 += __shfl_xor_sync(0xffffffffu, o0, off);
            o1 += __shfl_xor_sync(0xffffffffu, o1, off);
        }
        if (cl == 0) {
            int rg = r0 + r;
            if (base + rg < cnt) {
                float gsc = s_gate[rg] / s;
                size_t ob = (size_t)s_tok[rg] * OUT_;
                atomicAdd(out + ob + 0, o0 * gsc);
                atomicAdd(out + ob + 1, o1 * gsc);
            }
        }
    }
}

// ---------------- loss: cv^2(importance) + cv^2(load), ddof=1 ----------------
__global__ void loss_kernel(float* __restrict__ out, int out_size) {
    if (threadIdx.x != 0 || blockIdx.x != 0) return;
    double vi[E_], vl[E_], si = 0.0, sl = 0.0;
    for (int e = 0; e < E_; ++e) { vi[e] = (double)g_imp[e]; vl[e] = (double)g_load[e]; si += vi[e]; sl += vl[e]; }
    double mi = si / E_, ml = sl / E_;
    double qi = 0.0, ql = 0.0;
    for (int e = 0; e < E_; ++e) { double di = vi[e] - mi, dl = vl[e] - ml; qi += di * di; ql += dl * dl; }
    qi /= (E_ - 1); ql /= (E_ - 1);
    double loss = (qi / (mi * mi + 1e-10) + ql / (ml * ml + 1e-10)) * 1e-2;
    if (out_size > B_ * OUT_) out[B_ * OUT_] = (float)loss;
}

// ---------------- launch ----------------
extern "C" void kernel_launch(void* const* d_in, const int* in_sizes, int n_in,
                              void* d_out, int out_size) {
    (void)in_sizes; (void)n_in;
    const float* x    = (const float*)d_in[0];
    // d_in[1] = cat_prop (unused by the reference's output path)
    const float* wg   = (const float*)d_in[2];
    const float* W1   = (const float*)d_in[3];
    const float* b1   = (const float*)d_in[4];
    const float* W2   = (const float*)d_in[5];
    const float* b2   = (const float*)d_in[6];
    const float* Wout = (const float*)d_in[7];
    const float* bout = (const float*)d_in[8];
    float* out = (float*)d_out;

    cudaFuncSetAttribute(expert_kernel, cudaFuncAttributeMaxDynamicSharedMemorySize,
                         SMEM_EXPERT_BYTES);

    init_kernel<<<(B_ * OUT_ + 255) / 256, 256>>>(out, bout);
    gate_kernel<<<B_ / 32, 1024>>>(x, wg);
    expert_kernel<<<dim3(B_ / TM, E_), 256, SMEM_EXPERT_BYTES>>>(x, W1, b1, W2, b2, Wout, out);
    loss_kernel<<<1, 32>>>(out, out_size);
}